// round 5
// baseline (speedup 1.0000x reference)
#include <cuda_runtime.h>
#include <cuda_bf16.h>
#include <math.h>

// Scratch (device globals: allowed; no runtime allocation)
__device__ float g_dct[64 * 1024];     // coef-major: [k][block]
__device__ float g_spatial[1024];      // per-block sigmoid spatial gate
__device__ float g_sqpart[32][64];     // per-CTA partial sums of each coefficient
__device__ float g_out2d[256 * 256];   // final 2D map before broadcast

// ---------------------------------------------------------------------------
// Kernel 1: per-block 8x8 DCT + spatial gate + per-CTA coefficient partials
// grid = 32 CTAs x 32 threads, thread -> one 8x8 block (1024 blocks total)
// ---------------------------------------------------------------------------
__global__ void k_dct(const float* __restrict__ x,
                      const float* __restrict__ sse_w,
                      const float* __restrict__ sse_b)
{
    __shared__ float sD[64];
    __shared__ float sW[64];
    int tid = threadIdx.x;

    for (int idx = tid; idx < 64; idx += 32) {
        int k = idx >> 3, n = idx & 7;
        float v = 0.5f * cospif((float)((2 * n + 1) * k) / 16.0f);
        if (k == 0) v = 0.35355339059327373f;  // 1/(2*sqrt(2))
        sD[idx] = v;
        sW[idx] = sse_w[idx];
    }
    __syncthreads();

    int b = blockIdx.x * 32 + tid;   // block id 0..1023
    int R = b >> 5;                  // block row
    int C = b & 31;                  // block col

    // Load 8x8 block from channel 0 (stride 3)
    float a[64];
    const float* base = x + ((size_t)(R * 8) * 256 + C * 8) * 3;
#pragma unroll
    for (int i = 0; i < 8; i++)
#pragma unroll
        for (int j = 0; j < 8; j++)
            a[i * 8 + j] = base[(i * 256 + j) * 3];

    // t = D @ a
    float t[64];
#pragma unroll
    for (int i = 0; i < 8; i++)
#pragma unroll
        for (int j = 0; j < 8; j++) {
            float s = 0.f;
#pragma unroll
            for (int k = 0; k < 8; k++) s += sD[i * 8 + k] * a[k * 8 + j];
            t[i * 8 + j] = s;
        }

    // dct = t @ D^T ; store coef-major; accumulate spatial dot
    float sp = 0.f;
#pragma unroll
    for (int i = 0; i < 8; i++)
#pragma unroll
        for (int j = 0; j < 8; j++) {
            float s = 0.f;
#pragma unroll
            for (int l = 0; l < 8; l++) s += t[i * 8 + l] * sD[j * 8 + l];
            a[i * 8 + j] = s;                      // reuse a[] as dct
            g_dct[(i * 8 + j) * 1024 + b] = s;     // coalesced across lanes
            sp += sW[i * 8 + j] * s;
        }
    sp += sse_b[0];
    g_spatial[b] = 1.f / (1.f + expf(-sp));

    // Per-CTA partial sums of each coefficient (single warp: shuffle reduce)
    int lane = tid;  // 32-thread CTA == one warp
#pragma unroll
    for (int k = 0; k < 64; k++) {
        float v = a[k];
        v += __shfl_xor_sync(0xffffffffu, v, 16);
        v += __shfl_xor_sync(0xffffffffu, v, 8);
        v += __shfl_xor_sync(0xffffffffu, v, 4);
        v += __shfl_xor_sync(0xffffffffu, v, 2);
        v += __shfl_xor_sync(0xffffffffu, v, 1);
        if (lane == (k & 31)) g_sqpart[blockIdx.x][k] = v;
    }
}

// ---------------------------------------------------------------------------
// Kernel 2: tiny MLP (redundant per CTA) + gate + per-block 8x8 IDCT -> out2d
// grid = 32 CTAs x 32 threads, thread -> one 8x8 block
// ---------------------------------------------------------------------------
__global__ void k_idct(const float* __restrict__ fc1_w,
                       const float* __restrict__ fc1_b,
                       const float* __restrict__ fc2_w,
                       const float* __restrict__ fc2_b)
{
    __shared__ float sD[64], s_sq[64], s_h[32], s_sc[64];
    int tid = threadIdx.x;

    for (int idx = tid; idx < 64; idx += 32) {
        int k = idx >> 3, n = idx & 7;
        float v = 0.5f * cospif((float)((2 * n + 1) * k) / 16.0f);
        if (k == 0) v = 0.35355339059327373f;
        sD[idx] = v;
        float s = 0.f;
#pragma unroll
        for (int p = 0; p < 32; p++) s += g_sqpart[p][idx];
        s_sq[idx] = s * (1.0f / 1024.0f);
    }
    __syncthreads();

    // h = relu(fc1_w @ sq + fc1_b), 32 outputs
    {
        float s = fc1_b[tid];
#pragma unroll
        for (int c = 0; c < 64; c++) s += fc1_w[tid * 64 + c] * s_sq[c];
        s_h[tid] = fmaxf(s, 0.f);
    }
    __syncthreads();

    // scale_c = sigmoid(fc2_w @ h + fc2_b), 64 outputs
    for (int c = tid; c < 64; c += 32) {
        float s = fc2_b[c];
#pragma unroll
        for (int r = 0; r < 32; r++) s += fc2_w[c * 32 + r] * s_h[r];
        s_sc[c] = 1.f / (1.f + expf(-s));
    }
    __syncthreads();

    int b = blockIdx.x * 32 + tid;
    float sp = g_spatial[b];

    // Gate: y = dct * (dct >= 0 ? max(sc, sp) : min(sc, sp))
    float y[64];
#pragma unroll
    for (int k = 0; k < 64; k++) {
        float v = g_dct[k * 1024 + b];       // coalesced across lanes
        float sc = s_sc[k];
        float m = (v >= 0.f) ? fmaxf(sc, sp) : fminf(sc, sp);
        y[k] = v * m;
    }

    // t = D^T @ y
    float t[64];
#pragma unroll
    for (int i = 0; i < 8; i++)
#pragma unroll
        for (int l = 0; l < 8; l++) {
            float s = 0.f;
#pragma unroll
            for (int k = 0; k < 8; k++) s += sD[k * 8 + i] * y[k * 8 + l];
            t[i * 8 + l] = s;
        }

    // out = t @ D ; write 8x8 block into out2d (two float4 per row)
    int R = b >> 5, C = b & 31;
#pragma unroll
    for (int i = 0; i < 8; i++) {
        float r[8];
#pragma unroll
        for (int j = 0; j < 8; j++) {
            float s = 0.f;
#pragma unroll
            for (int l = 0; l < 8; l++) s += t[i * 8 + l] * sD[l * 8 + j];
            r[j] = s;
        }
        float4* dst = (float4*)&g_out2d[(R * 8 + i) * 256 + C * 8];
        dst[0] = make_float4(r[0], r[1], r[2], r[3]);
        dst[1] = make_float4(r[4], r[5], r[6], r[7]);
    }
}

// ---------------------------------------------------------------------------
// Kernel 3: broadcast out2d (256 KB) to all planes of d_out (write-bound)
// grid = (64, ceil(planes/16)) x 256 threads; 1 L2 read amortized over 16 stores
// ---------------------------------------------------------------------------
__global__ void k_bcast(float4* __restrict__ out, int planes)
{
    int q = blockIdx.x * 256 + threadIdx.x;         // 0..16383 (float4 within plane)
    const float4* src = (const float4*)g_out2d;
    float4 v = src[q];
    int p0 = blockIdx.y * 16;
#pragma unroll
    for (int pp = 0; pp < 16; pp++) {
        int p = p0 + pp;
        if (p < planes) out[(size_t)p * 16384 + q] = v;
    }
}

extern "C" void kernel_launch(void* const* d_in, const int* in_sizes, int n_in,
                              void* d_out, int out_size)
{
    const float* x      = (const float*)d_in[0];
    const float* fc1_w  = (const float*)d_in[1];
    const float* fc1_b  = (const float*)d_in[2];
    const float* fc2_w  = (const float*)d_in[3];
    const float* fc2_b  = (const float*)d_in[4];
    const float* sse_w  = (const float*)d_in[5];
    const float* sse_b  = (const float*)d_in[6];
    // d_in[7] = bs (unused; plane count derived from out_size)

    int planes = out_size / (256 * 256);   // 64*3 = 192

    k_dct<<<32, 32>>>(x, sse_w, sse_b);
    k_idct<<<32, 32>>>(fc1_w, fc1_b, fc2_w, fc2_b);

    dim3 grid(64, (planes + 15) / 16);
    k_bcast<<<grid, 256>>>((float4*)d_out, planes);
}

// round 6
// speedup vs baseline: 1.3876x; 1.3876x over previous
#include <cuda_runtime.h>
#include <cuda_bf16.h>
#include <math.h>

// Scratch (device globals: allowed; no runtime allocation)
__device__ float g_dct[1024 * 64];     // block-major: [block][coef]
__device__ float g_spatial[1024];      // per-block sigmoid spatial gate
__device__ float g_sqpart[32][64];     // per-CTA partial sums of each coefficient
__device__ float g_out2d[256 * 256];   // final 2D map before broadcast

// ---------------------------------------------------------------------------
// Kernel 1: 8x8 DCT (8 threads per block, column-decomposed) + spatial gate
//           + per-CTA coefficient partial sums
// grid = 32 CTAs x 256 threads; thread -> (block b, column j); 8192 threads
// ---------------------------------------------------------------------------
__global__ void k_dct(const float* __restrict__ x,
                      const float* __restrict__ sse_w,
                      const float* __restrict__ sse_b)
{
    __shared__ float sD[64];
    __shared__ float sW[64];
    __shared__ float red[8][64];
    int tid = threadIdx.x;
    int w = tid >> 5, lane = tid & 31;

    if (tid < 64) {
        int k = tid >> 3, n = tid & 7;
        float v = 0.5f * cospif((float)((2 * n + 1) * k) / 16.0f);
        if (k == 0) v = 0.35355339059327373f;  // 1/(2*sqrt(2))
        sD[tid] = v;
        sW[tid] = sse_w[tid];
    }
    __syncthreads();

    int g = blockIdx.x * 256 + tid;
    int b = g >> 3;          // block id 0..1023
    int j = g & 7;           // column within 8x8 block
    int R = b >> 5, C = b & 31;
    int baseLane = lane & 24;  // start of this block's 8-lane group in warp

    // Load column j of the 8x8 block from channel 0 (stride 3)
    float a[8];
    const float* base = x + ((size_t)(R * 8) * 256 + C * 8 + j) * 3;
#pragma unroll
    for (int k = 0; k < 8; k++)
        a[k] = base[k * 256 * 3];

    // Row pass (thread-local): t[i] = sum_k D[i][k] * a[k]
    float t[8];
#pragma unroll
    for (int i = 0; i < 8; i++) {
        float s = 0.f;
#pragma unroll
        for (int k = 0; k < 8; k++) s += sD[i * 8 + k] * a[k];
        t[i] = s;
    }

    // Column pass via shuffles: dct[i][j] = sum_l t[i][l] * D[j][l]
    float d[8];
    float sp = 0.f;
#pragma unroll
    for (int i = 0; i < 8; i++) {
        float s = 0.f;
#pragma unroll
        for (int l = 0; l < 8; l++) {
            float tl = __shfl_sync(0xffffffffu, t[i], baseLane + l);
            s += tl * sD[j * 8 + l];
        }
        d[i] = s;
        g_dct[b * 64 + i * 8 + j] = s;         // 4x32B segments per warp store
        sp += sW[i * 8 + j] * s;
    }

    // Spatial gate: reduce sp over the 8 lanes of this block
    sp += __shfl_xor_sync(0xffffffffu, sp, 1);
    sp += __shfl_xor_sync(0xffffffffu, sp, 2);
    sp += __shfl_xor_sync(0xffffffffu, sp, 4);
    if (j == 0) g_spatial[b] = 1.f / (1.f + expf(-(sp + sse_b[0])));

    // Coefficient partial sums: reduce over the 4 blocks in this warp
    float bsum[8];
#pragma unroll
    for (int i = 0; i < 8; i++) {
        float v = d[i];
        v += __shfl_xor_sync(0xffffffffu, v, 8);
        v += __shfl_xor_sync(0xffffffffu, v, 16);
        bsum[i] = v;
    }
    if (lane < 8) {
#pragma unroll
        for (int i = 0; i < 8; i++) red[w][i * 8 + lane] = bsum[i];
    }
    __syncthreads();

    // Sum the 8 warps' partials -> one partial per CTA per coefficient
    if (tid < 64) {
        float s = 0.f;
#pragma unroll
        for (int p = 0; p < 8; p++) s += red[p][tid];
        g_sqpart[blockIdx.x][tid] = s;
    }
}

// ---------------------------------------------------------------------------
// Kernel 2: tiny MLP (redundant per CTA) + gate + 8x8 IDCT -> out2d
// grid = 32 CTAs x 256 threads; thread -> (block b, column j)
// ---------------------------------------------------------------------------
__global__ void k_idct(const float* __restrict__ fc1_w,
                       const float* __restrict__ fc1_b,
                       const float* __restrict__ fc2_w,
                       const float* __restrict__ fc2_b)
{
    __shared__ float sD[64], s_sq[64], s_h[32], s_sc[64];
    int tid = threadIdx.x;
    int lane = tid & 31;

    if (tid < 64) {
        int k = tid >> 3, n = tid & 7;
        float v = 0.5f * cospif((float)((2 * n + 1) * k) / 16.0f);
        if (k == 0) v = 0.35355339059327373f;
        sD[tid] = v;
        float s = 0.f;
#pragma unroll
        for (int p = 0; p < 32; p++) s += g_sqpart[p][tid];
        s_sq[tid] = s * (1.0f / 1024.0f);
    }
    __syncthreads();

    // h = relu(fc1_w @ sq + fc1_b), 32 outputs
    if (tid < 32) {
        float s = fc1_b[tid];
#pragma unroll
        for (int c = 0; c < 64; c++) s += fc1_w[tid * 64 + c] * s_sq[c];
        s_h[tid] = fmaxf(s, 0.f);
    }
    __syncthreads();

    // scale_c = sigmoid(fc2_w @ h + fc2_b), 64 outputs
    if (tid < 64) {
        float s = fc2_b[tid];
#pragma unroll
        for (int r = 0; r < 32; r++) s += fc2_w[tid * 32 + r] * s_h[r];
        s_sc[tid] = 1.f / (1.f + expf(-s));
    }
    __syncthreads();

    int g = blockIdx.x * 256 + tid;
    int b = g >> 3;
    int j = g & 7;
    int R = b >> 5, C = b & 31;
    int baseLane = lane & 24;

    float sp = g_spatial[b];

    // Gate: y = dct * (dct >= 0 ? max(sc, sp) : min(sc, sp))
    float y[8];
#pragma unroll
    for (int i = 0; i < 8; i++) {
        float v = g_dct[b * 64 + i * 8 + j];
        float sc = s_sc[i * 8 + j];
        float m = (v >= 0.f) ? fmaxf(sc, sp) : fminf(sc, sp);
        y[i] = v * m;
    }

    // Row pass (thread-local): u[i] = sum_k D[k][i] * y[k]   (D^T @ Y)
    float u[8];
#pragma unroll
    for (int i = 0; i < 8; i++) {
        float s = 0.f;
#pragma unroll
        for (int k = 0; k < 8; k++) s += sD[k * 8 + i] * y[k];
        u[i] = s;
    }

    // Column pass via shuffles: out[i][j] = sum_l u[i][l] * D[l][j]
    // Writes: per warp, fixed i -> 32 consecutive floats (fully coalesced)
#pragma unroll
    for (int i = 0; i < 8; i++) {
        float s = 0.f;
#pragma unroll
        for (int l = 0; l < 8; l++) {
            float ul = __shfl_sync(0xffffffffu, u[i], baseLane + l);
            s += ul * sD[l * 8 + j];
        }
        g_out2d[(R * 8 + i) * 256 + C * 8 + j] = s;
    }
}

// ---------------------------------------------------------------------------
// Kernel 3: broadcast out2d (256 KB) to all planes of d_out (write-bound)
// grid = (64, ceil(planes/16)) x 256 threads; 1 L2 read per 16 plane stores
// ---------------------------------------------------------------------------
__global__ void k_bcast(float4* __restrict__ out, int planes)
{
    int q = blockIdx.x * 256 + threadIdx.x;         // float4 index within plane
    const float4* src = (const float4*)g_out2d;
    float4 v = src[q];
    int p0 = blockIdx.y * 16;
#pragma unroll
    for (int pp = 0; pp < 16; pp++) {
        int p = p0 + pp;
        if (p < planes) out[(size_t)p * 16384 + q] = v;
    }
}

extern "C" void kernel_launch(void* const* d_in, const int* in_sizes, int n_in,
                              void* d_out, int out_size)
{
    const float* x      = (const float*)d_in[0];
    const float* fc1_w  = (const float*)d_in[1];
    const float* fc1_b  = (const float*)d_in[2];
    const float* fc2_w  = (const float*)d_in[3];
    const float* fc2_b  = (const float*)d_in[4];
    const float* sse_w  = (const float*)d_in[5];
    const float* sse_b  = (const float*)d_in[6];
    // d_in[7] = bs (unused; plane count derived from out_size)

    int planes = out_size / (256 * 256);   // 64*3 = 192

    k_dct<<<32, 256>>>(x, sse_w, sse_b);
    k_idct<<<32, 256>>>(fc1_w, fc1_b, fc2_w, fc2_b);

    dim3 grid(64, (planes + 15) / 16);
    k_bcast<<<grid, 256>>>((float4*)d_out, planes);
}

// round 8
// speedup vs baseline: 1.3897x; 1.0015x over previous
#include <cuda_runtime.h>
#include <cuda_bf16.h>
#include <math.h>

#define NCTA 128

// Scratch (device globals: allowed; no runtime allocation)
__device__ float g_dct[1024 * 64];     // block-major: [block][coef]
__device__ float g_spatial[1024];      // per-block sigmoid spatial gate
__device__ float g_sqpart[NCTA][64];   // per-CTA partial sums of each coefficient

// ---------------------------------------------------------------------------
// Kernel 1: 8x8 DCT (8 threads per block) + spatial gate + coefficient partials
// grid = 128 CTAs x 64 threads; thread -> (block b, column j); 8 blocks/CTA
// ---------------------------------------------------------------------------
__global__ void __launch_bounds__(64)
k_dct(const float* __restrict__ x,
      const float* __restrict__ sse_w,
      const float* __restrict__ sse_b)
{
    __shared__ float sD[64];
    __shared__ float red[2][64];
    int tid = threadIdx.x;             // 0..63
    int w = tid >> 5, lane = tid & 31;

    {
        int k = tid >> 3, n = tid & 7;
        float v = 0.5f * cospif((float)((2 * n + 1) * k) / 16.0f);
        if (k == 0) v = 0.35355339059327373f;  // 1/(2*sqrt(2))
        sD[tid] = v;
    }
    __syncthreads();

    int g = blockIdx.x * 64 + tid;
    int b = g >> 3;                    // block id 0..1023
    int j = g & 7;                     // column within 8x8 block
    int R = b >> 5, C = b & 31;
    int baseLane = lane & 24;          // this block's 8-lane group in the warp

    // Load column j of the 8x8 block from channel 0 (stride 3)
    float a[8];
    const float* base = x + ((size_t)(R * 8) * 256 + C * 8 + j) * 3;
#pragma unroll
    for (int k = 0; k < 8; k++)
        a[k] = base[k * 256 * 3];

    // Row pass (thread-local): t[i] = sum_k D[i][k] * a[k]
    float t[8];
#pragma unroll
    for (int i = 0; i < 8; i++) {
        float s = 0.f;
#pragma unroll
        for (int k = 0; k < 8; k++) s += sD[i * 8 + k] * a[k];
        t[i] = s;
    }

    // Column pass via shuffles: d[i] = dct[i][j] = sum_l t[i][l] * D[j][l]
    float d[8];
    float sp = 0.f;
#pragma unroll
    for (int i = 0; i < 8; i++) {
        float s = 0.f;
#pragma unroll
        for (int l = 0; l < 8; l++) {
            float tl = __shfl_sync(0xffffffffu, t[i], baseLane + l);
            s += tl * sD[j * 8 + l];
        }
        d[i] = s;
        g_dct[b * 64 + i * 8 + j] = s;
        sp += sse_w[i * 8 + j] * s;
    }

    // Spatial gate: reduce sp over the 8 lanes of this block
    sp += __shfl_xor_sync(0xffffffffu, sp, 1);
    sp += __shfl_xor_sync(0xffffffffu, sp, 2);
    sp += __shfl_xor_sync(0xffffffffu, sp, 4);
    if (j == 0) g_spatial[b] = 1.f / (1.f + expf(-(sp + sse_b[0])));

    // Coefficient partial sums over the 2 blocks... (4 blocks per warp: xor 8,16)
#pragma unroll
    for (int i = 0; i < 8; i++) {
        float v = d[i];
        v += __shfl_xor_sync(0xffffffffu, v, 8);
        v += __shfl_xor_sync(0xffffffffu, v, 16);
        if (lane < 8) red[w][i * 8 + lane] = v;
    }
    __syncthreads();
    g_sqpart[blockIdx.x][tid] = red[0][tid] + red[1][tid];
}

// ---------------------------------------------------------------------------
// Kernel 2: MLP (redundant per CTA) + gate + IDCT + direct broadcast to d_out
// grid = 128 CTAs x 256 threads. Threads 0..63 do the IDCT for this CTA's
// 8 blocks (8 rows x 64 cols pixel region), staged in smem; then all 256
// threads broadcast the 2KB region to every plane with float4 stores.
// ---------------------------------------------------------------------------
__global__ void __launch_bounds__(256)
k_idct_bcast(const float* __restrict__ fc1_w,
             const float* __restrict__ fc1_b,
             const float* __restrict__ fc2_w,
             const float* __restrict__ fc2_b,
             float* __restrict__ out, int planes)
{
    __shared__ float sD[64], s_sq[64], s_h[32], s_sc[64];
    __shared__ float s_out[8][64];     // 8 pixel rows x 64 pixel cols

    int tid = threadIdx.x;
    int lane = tid & 31;

    if (tid < 64) {
        int k = tid >> 3, n = tid & 7;
        float v = 0.5f * cospif((float)((2 * n + 1) * k) / 16.0f);
        if (k == 0) v = 0.35355339059327373f;
        sD[tid] = v;
        float s = 0.f;
#pragma unroll
        for (int p = 0; p < NCTA; p++) s += g_sqpart[p][tid];
        s_sq[tid] = s * (1.0f / 1024.0f);
    }
    __syncthreads();

    // h = relu(fc1_w @ sq + fc1_b), 32 outputs
    if (tid < 32) {
        float s = fc1_b[tid];
#pragma unroll
        for (int c = 0; c < 64; c++) s += fc1_w[tid * 64 + c] * s_sq[c];
        s_h[tid] = fmaxf(s, 0.f);
    }
    __syncthreads();

    // scale_c = sigmoid(fc2_w @ h + fc2_b), 64 outputs
    if (tid < 64) {
        float s = fc2_b[tid];
#pragma unroll
        for (int r = 0; r < 32; r++) s += fc2_w[tid * 32 + r] * s_h[r];
        s_sc[tid] = 1.f / (1.f + expf(-s));
    }
    __syncthreads();

    int R  = (blockIdx.x * 8) >> 5;        // shared by all 8 blocks of this CTA
    int C0 = (blockIdx.x * 8) & 31;        // first block column

    if (tid < 64) {
        int b = blockIdx.x * 8 + (tid >> 3);
        int j = tid & 7;
        int baseLane = lane & 24;
        float sp = g_spatial[b];

        // Gate: y = dct * (dct >= 0 ? max(sc, sp) : min(sc, sp))
        float y[8];
#pragma unroll
        for (int i = 0; i < 8; i++) {
            float v = g_dct[b * 64 + i * 8 + j];
            float sc = s_sc[i * 8 + j];
            float m = (v >= 0.f) ? fmaxf(sc, sp) : fminf(sc, sp);
            y[i] = v * m;
        }

        // Row pass: u[i] = sum_k D[k][i] * y[k]   (D^T @ Y)
        float u[8];
#pragma unroll
        for (int i = 0; i < 8; i++) {
            float s = 0.f;
#pragma unroll
            for (int k = 0; k < 8; k++) s += sD[k * 8 + i] * y[k];
            u[i] = s;
        }

        // Column pass via shuffles -> stage pixel region in smem
        int col = (tid >> 3) * 8 + j;      // 0..63 within region
#pragma unroll
        for (int i = 0; i < 8; i++) {
            float s = 0.f;
#pragma unroll
            for (int l = 0; l < 8; l++) {
                float ul = __shfl_sync(0xffffffffu, u[i], baseLane + l);
                s += ul * sD[l * 8 + j];
            }
            s_out[i][col] = s;
        }
    }
    __syncthreads();

    // Broadcast: region (8 rows x 64 cols) -> every plane, float4 stores
    // f4 layout: idx = (p*8 + row)*16 + c4
    float4* outf4 = (float4*)out;
    const float4* src = (const float4*)s_out;
    size_t rowStride = 64;                           // f4 per 256-float row
    size_t base = (size_t)(R * 8) * 64 + C0 * 2;     // f4 offset of region row 0
    int total = planes * 8 * 16;
    for (int idx = tid; idx < total; idx += 256) {
        int p   = idx >> 7;          // plane
        int rem = idx & 127;
        int row = rem >> 4;
        int c4  = rem & 15;
        float4 v = src[row * 16 + c4];
        outf4[(size_t)p * 16384 + base + (size_t)row * rowStride + c4] = v;
    }
}

extern "C" void kernel_launch(void* const* d_in, const int* in_sizes, int n_in,
                              void* d_out, int out_size)
{
    const float* x      = (const float*)d_in[0];
    const float* fc1_w  = (const float*)d_in[1];
    const float* fc1_b  = (const float*)d_in[2];
    const float* fc2_w  = (const float*)d_in[3];
    const float* fc2_b  = (const float*)d_in[4];
    const float* sse_w  = (const float*)d_in[5];
    const float* sse_b  = (const float*)d_in[6];
    // d_in[7] = bs (unused; plane count derived from out_size)

    int planes = out_size / (256 * 256);   // 64*3 = 192

    k_dct<<<NCTA, 64>>>(x, sse_w, sse_b);
    k_idct_bcast<<<NCTA, 256>>>(fc1_w, fc1_b, fc2_w, fc2_b, (float*)d_out, planes);
}